// round 8
// baseline (speedup 1.0000x reference)
#include <cuda_runtime.h>

// ---------------------------------------------------------------------------
// AutoregressiveGRUWithAttention
//   B=1024, L=64, T=128, IN=13, H=64, OUT=13
//
// 128 persistent blocks x 256 threads; 8 batch elements per block; thread
// (g, j) owns hidden channel j for 2 batches. Whole 192-step recurrence runs
// inside the block (batches independent -> no grid sync).
//
// Attention: per-(batch,channel) ONLINE softmax over the growing prediction
// buffer (m, s, acc folded with rescaling) — exactly equal to the reference's
// masked full-buffer softmax (NEG entries underflow to 0 in fp32).
//
// Decoder is autoregressive: GRU input at step t is y_{t-1} (scan carry slot 3
// is replaced by y each step) — gi recomputed per step from the staged y.
// ---------------------------------------------------------------------------

namespace {
constexpr int B_   = 1024;
constexpr int L_   = 64;
constexpr int T_   = 128;
constexpr int IN_  = 13;
constexpr int H_   = 64;
constexpr int H3_  = 192;
constexpr int OUT_ = 13;
constexpr int WP_  = 68;   // padded row stride (floats) -> conflict-free float4
constexpr int NB_  = 8;    // batches per block
constexpr int THREADS_ = 256;
constexpr int BLOCKS_  = B_ / NB_;   // 128

// shared-memory layout (in floats)
constexpr int SM_WHH = 0;                       // [192][68]
constexpr int SM_WA  = SM_WHH + H3_ * WP_;      // [64][68]
constexpr int SM_WF  = SM_WA  + H_  * WP_;      // [16][68] (13 rows used)
constexpr int SM_WIH = SM_WF  + 16  * WP_;      // [192][13]
constexpr int SM_BIH = SM_WIH + H3_ * IN_;      // [192]
constexpr int SM_BHH = SM_BIH + H3_;            // [192]
constexpr int SM_BA  = SM_BHH + H3_;            // [64]
constexpr int SM_BF  = SM_BA  + H_;             // [16]
constexpr int SM_H   = SM_BF  + 16;             // [8][68]  hidden state
constexpr int SM_O   = SM_H   + NB_ * WP_;      // [8][68]  o vector
constexpr int SM_X   = SM_O   + NB_ * WP_;      // [8][16]  x_t staging
constexpr int SM_NIN = SM_X   + NB_ * 16;       // [8][16]  decoder input (y_prev)
constexpr int SM_LEN = SM_NIN + NB_ * 16;       // [8] ints
constexpr int SM_FLOATS = SM_LEN + NB_;
constexpr int SMEM_BYTES = SM_FLOATS * 4;
}

__device__ __forceinline__ float sigmoid_(float a) {
    return __fdividef(1.f, 1.f + __expf(-a));
}
__device__ __forceinline__ float tanh_(float a) {
    float c  = fminf(fmaxf(a, -15.f), 15.f);
    float e2 = __expf(2.f * c);
    return __fdividef(e2 - 1.f, e2 + 1.f);
}
__device__ __forceinline__ float dot4_(float4 a, float4 b) {
    return a.x * b.x + a.y * b.y + a.z * b.z + a.w * b.w;
}

__global__ void __launch_bounds__(THREADS_, 1)
gru_attn_kernel(const float* __restrict__ x, const int* __restrict__ lengths,
                const float* __restrict__ Wih, const float* __restrict__ Whh,
                const float* __restrict__ bih, const float* __restrict__ bhh,
                const float* __restrict__ Wf,  const float* __restrict__ bf,
                const float* __restrict__ Wa,  const float* __restrict__ ba,
                float* __restrict__ out)
{
    extern __shared__ float sm[];
    float* sWhh = sm + SM_WHH;
    float* sWa  = sm + SM_WA;
    float* sWf  = sm + SM_WF;
    float* sWih = sm + SM_WIH;
    float* sbih = sm + SM_BIH;
    float* sbhh = sm + SM_BHH;
    float* sba  = sm + SM_BA;
    float* sbf  = sm + SM_BF;
    float* sh   = sm + SM_H;
    float* so   = sm + SM_O;
    float* sx   = sm + SM_X;
    float* snin = sm + SM_NIN;
    int*   slen = (int*)(sm + SM_LEN);

    const int tid = threadIdx.x;
    const int j   = tid & 63;         // hidden channel
    const int g   = tid >> 6;         // group 0..3
    const int bb0 = g * 2;
    const int bb1 = g * 2 + 1;
    const int b0  = blockIdx.x * NB_;

    // ---- stage weights in shared (padded rows for bank-conflict-free float4)
    for (int idx = tid; idx < H3_ * H_; idx += THREADS_) {
        int r = idx >> 6, c = idx & 63;
        sWhh[r * WP_ + c] = Whh[idx];
    }
    for (int idx = tid; idx < H_ * H_; idx += THREADS_) {
        int r = idx >> 6, c = idx & 63;
        sWa[r * WP_ + c] = Wa[idx];
    }
    for (int idx = tid; idx < OUT_ * H_; idx += THREADS_) {
        int r = idx >> 6, c = idx & 63;
        sWf[r * WP_ + c] = Wf[idx];
    }
    for (int idx = tid; idx < H3_ * IN_; idx += THREADS_) sWih[idx] = Wih[idx];
    if (tid < H3_) { sbih[tid] = bih[tid]; sbhh[tid] = bhh[tid]; }
    if (tid < H_)  sba[tid] = ba[tid];
    if (tid < OUT_) sbf[tid] = bf[tid];
    for (int idx = tid; idx < NB_ * WP_; idx += THREADS_) { sh[idx] = 0.f; so[idx] = 0.f; }
    if (tid < NB_) slen[tid] = lengths[b0 + tid];
    __syncthreads();

    const float4* whr = (const float4*)(sWhh + j * WP_);
    const float4* whz = (const float4*)(sWhh + (64 + j) * WP_);
    const float4* whn = (const float4*)(sWhh + (128 + j) * WP_);
    const float4* war = (const float4*)(sWa + j * WP_);
    const float4* h0v = (const float4*)(sh + bb0 * WP_);
    const float4* h1v = (const float4*)(sh + bb1 * WP_);
    const float4* o0v = (const float4*)(so + bb0 * WP_);
    const float4* o1v = (const float4*)(so + bb1 * WP_);

    const int len0 = slen[bb0];
    const int len1 = slen[bb1];

    // =======================  ENCODER  =======================
    for (int t = 0; t < L_; ++t) {
        // stage x_t for the 8 batches (104 values)
        if (tid < NB_ * IN_) {
            int bb = tid / IN_, i = tid - bb * IN_;
            sx[bb * 16 + i] = x[(b0 + bb) * (L_ * IN_) + t * IN_ + i];
        }
        __syncthreads();   // sx + previous-step h visible

        // gi = Wih @ x + bih
        float ir0 = sbih[j], iz0 = sbih[64 + j], in0 = sbih[128 + j];
        float ir1 = ir0, iz1 = iz0, in1 = in0;
        #pragma unroll
        for (int i = 0; i < IN_; ++i) {
            float wr = sWih[j * IN_ + i];
            float wz = sWih[(64 + j) * IN_ + i];
            float wn = sWih[(128 + j) * IN_ + i];
            float u = sx[bb0 * 16 + i], v = sx[bb1 * 16 + i];
            ir0 += wr * u; iz0 += wz * u; in0 += wn * u;
            ir1 += wr * v; iz1 += wz * v; in1 += wn * v;
        }
        // gh = Whh @ h + bhh
        float hr0 = sbhh[j], hz0 = sbhh[64 + j], hn0 = sbhh[128 + j];
        float hr1 = hr0, hz1 = hz0, hn1 = hn0;
        #pragma unroll
        for (int q = 0; q < 16; ++q) {
            float4 wr = whr[q], wz = whz[q], wn = whn[q];
            float4 u = h0v[q], v = h1v[q];
            hr0 += dot4_(wr, u); hz0 += dot4_(wz, u); hn0 += dot4_(wn, u);
            hr1 += dot4_(wr, v); hz1 += dot4_(wz, v); hn1 += dot4_(wn, v);
        }
        float r0 = sigmoid_(ir0 + hr0), z0 = sigmoid_(iz0 + hz0);
        float n0 = tanh_(in0 + r0 * hn0);
        float hp0 = sh[bb0 * WP_ + j];
        float hv0 = (t < len0) ? ((1.f - z0) * n0 + z0 * hp0) : hp0;

        float r1 = sigmoid_(ir1 + hr1), z1 = sigmoid_(iz1 + hz1);
        float n1 = tanh_(in1 + r1 * hn1);
        float hp1 = sh[bb1 * WP_ + j];
        float hv1 = (t < len1) ? ((1.f - z1) * n1 + z1 * hp1) : hp1;

        __syncthreads();   // all readers of sh done
        sh[bb0 * WP_ + j] = hv0;
        sh[bb1 * WP_ + j] = hv1;
    }
    __syncthreads();

    // outs[-1] is nonzero only when lengths == L (then it equals final h)
    so[bb0 * WP_ + j] = (len0 == L_) ? sh[bb0 * WP_ + j] : 0.f;
    so[bb1 * WP_ + j] = (len1 == L_) ? sh[bb1 * WP_ + j] : 0.f;
    __syncthreads();

    // nin = outs[-1] @ Wf^T + bf  -> decoder input for step 0
    if (j < OUT_) {
        float y0 = sbf[j], y1 = sbf[j];
        const float4* wf = (const float4*)(sWf + j * WP_);
        #pragma unroll
        for (int q = 0; q < 16; ++q) {
            float4 w = wf[q];
            y0 += dot4_(w, o0v[q]);
            y1 += dot4_(w, o1v[q]);
        }
        snin[bb0 * 16 + j] = y0;
        snin[bb1 * 16 + j] = y1;
    }
    __syncthreads();

    // =======================  DECODER  =======================
    // online softmax state per (batch, channel)
    float m0 = -1e30f, s0 = 0.f, a0 = 0.f;
    float m1 = -1e30f, s1 = 0.f, a1 = 0.f;

    for (int t = 0; t < T_; ++t) {
        // gi = Wih @ y_prev + bih  (autoregressive: y_prev staged in snin)
        float ir0 = sbih[j], iz0 = sbih[64 + j], in0 = sbih[128 + j];
        float ir1 = ir0, iz1 = iz0, in1 = in0;
        #pragma unroll
        for (int i = 0; i < IN_; ++i) {
            float wr = sWih[j * IN_ + i];
            float wz = sWih[(64 + j) * IN_ + i];
            float wn = sWih[(128 + j) * IN_ + i];
            float u = snin[bb0 * 16 + i], v = snin[bb1 * 16 + i];
            ir0 += wr * u; iz0 += wz * u; in0 += wn * u;
            ir1 += wr * v; iz1 += wz * v; in1 += wn * v;
        }

        // gh = Whh @ h + bhh
        float hr0 = sbhh[j], hz0 = sbhh[64 + j], hn0 = sbhh[128 + j];
        float hr1 = hr0, hz1 = hz0, hn1 = hn0;
        #pragma unroll
        for (int q = 0; q < 16; ++q) {
            float4 wr = whr[q], wz = whz[q], wn = whn[q];
            float4 u = h0v[q], v = h1v[q];
            hr0 += dot4_(wr, u); hz0 += dot4_(wz, u); hn0 += dot4_(wn, u);
            hr1 += dot4_(wr, v); hz1 += dot4_(wz, v); hn1 += dot4_(wn, v);
        }
        float r0 = sigmoid_(ir0 + hr0), z0 = sigmoid_(iz0 + hz0);
        float n0 = tanh_(in0 + r0 * hn0);
        float hp0 = sh[bb0 * WP_ + j];
        float hne0 = (1.f - z0) * n0 + z0 * hp0;
        float att0 = (t == 0) ? 0.f : __fdividef(a0, s0);
        float o0 = hne0 + att0;

        float r1 = sigmoid_(ir1 + hr1), z1 = sigmoid_(iz1 + hz1);
        float n1 = tanh_(in1 + r1 * hn1);
        float hp1 = sh[bb1 * WP_ + j];
        float hne1 = (1.f - z1) * n1 + z1 * hp1;
        float att1 = (t == 0) ? 0.f : __fdividef(a1, s1);
        float o1 = hne1 + att1;

        __syncthreads();   // (A) readers of sh / snin / so done
        sh[bb0 * WP_ + j] = hne0;
        sh[bb1 * WP_ + j] = hne1;
        so[bb0 * WP_ + j] = o0;
        so[bb1 * WP_ + j] = o1;
        __syncthreads();   // (B) writes visible

        // logit l[j] = Wa[j,:] . o + ba[j]
        float l0 = sba[j], l1 = sba[j];
        #pragma unroll
        for (int q = 0; q < 16; ++q) {
            float4 w = war[q];
            l0 += dot4_(w, o0v[q]);
            l1 += dot4_(w, o1v[q]);
        }

        // y = o @ Wf^T + bf ; write to output and stage as next decoder input
        if (j < OUT_) {
            float y0 = sbf[j], y1 = sbf[j];
            const float4* wf = (const float4*)(sWf + j * WP_);
            #pragma unroll
            for (int q = 0; q < 16; ++q) {
                float4 w = wf[q];
                y0 += dot4_(w, o0v[q]);
                y1 += dot4_(w, o1v[q]);
            }
            out[((b0 + bb0) * T_ + t) * OUT_ + j] = y0;
            out[((b0 + bb1) * T_ + t) * OUT_ + j] = y1;
            snin[bb0 * 16 + j] = y0;
            snin[bb1 * 16 + j] = y1;
        }

        // online softmax update with the entry just written (buf[t] = o)
        float mn0 = fmaxf(m0, l0);
        float c0 = __expf(m0 - mn0), e0 = __expf(l0 - mn0);
        s0 = s0 * c0 + e0;
        a0 = a0 * c0 + e0 * o0;
        m0 = mn0;

        float mn1 = fmaxf(m1, l1);
        float c1 = __expf(m1 - mn1), e1 = __expf(l1 - mn1);
        s1 = s1 * c1 + e1;
        a1 = a1 * c1 + e1 * o1;
        m1 = mn1;

        __syncthreads();   // (C) snin (y) visible for next step's gi
    }
}

extern "C" void kernel_launch(void* const* d_in, const int* in_sizes, int n_in,
                              void* d_out, int out_size) {
    // Inputs in metadata order: x, lengths, output_length, Wih, Whh, bih, bhh,
    // Wf, bf, Wa, ba. Mapped by element count (bih before bhh in order).
    const float* xp   = nullptr;
    const int*   lenp = nullptr;
    const float *Wihp = nullptr, *Whhp = nullptr, *bihp = nullptr, *bhhp = nullptr;
    const float *Wfp = nullptr, *bfp = nullptr, *Wap = nullptr, *bap = nullptr;

    for (int i = 0; i < n_in; ++i) {
        switch (in_sizes[i]) {
            case 1024 * 64 * 13: xp   = (const float*)d_in[i]; break;
            case 1024:           lenp = (const int*)d_in[i];   break;
            case 192 * 13:       Wihp = (const float*)d_in[i]; break;
            case 192 * 64:       Whhp = (const float*)d_in[i]; break;
            case 192:
                if (!bihp) bihp = (const float*)d_in[i];
                else       bhhp = (const float*)d_in[i];
                break;
            case 13 * 64:        Wfp  = (const float*)d_in[i]; break;
            case 13:             bfp  = (const float*)d_in[i]; break;
            case 64 * 64:        Wap  = (const float*)d_in[i]; break;
            case 64:             bap  = (const float*)d_in[i]; break;
            default: break;   // output_length scalar -> hardcoded T=128
        }
    }

    cudaFuncSetAttribute(gru_attn_kernel,
                         cudaFuncAttributeMaxDynamicSharedMemorySize, SMEM_BYTES);

    gru_attn_kernel<<<BLOCKS_, THREADS_, SMEM_BYTES>>>(
        xp, lenp, Wihp, Whhp, bihp, bhhp, Wfp, bfp, Wap, bap, (float*)d_out);
}